// round 16
// baseline (speedup 1.0000x reference)
#include <cuda_runtime.h>
#include <cuda_bf16.h>
#include <math.h>

// Problem constants
#define BB 2
#define II 768
#define CA 768
#define CS 384
#define CZ 128
#define HH 16
#define DD 48
#define HC 768
#define ROWS (BB*II)          // 1536
#define EPS 1e-5f

// ---------------- device scratch (no allocations allowed) ----------------
__device__ float g_aln  [ROWS*CA];
__device__ float g_sln  [ROWS*CS];
__device__ float g_t1   [ROWS*CA];
__device__ float g_t2   [ROWS*CA];
__device__ float g_a2   [ROWS*CA];
__device__ float g_q    [ROWS*HC];
__device__ float g_k    [ROWS*HC];
__device__ float g_v    [ROWS*HC];
__device__ float g_gbuf [ROWS*HC];
__device__ float g_gate [ROWS*CA];
__device__ float g_scores[(size_t)BB*HH*II*II];   // [b][h][i][j]  ~75.5 MB
__device__ float g_o    [ROWS*HC];

// ---------------- bf16 helpers ----------------
__device__ __forceinline__ void mma_bf16(float* d, const unsigned* a, const unsigned* b) {
    asm volatile(
        "mma.sync.aligned.m16n8k16.row.col.f32.bf16.bf16.f32 "
        "{%0,%1,%2,%3}, {%4,%5,%6,%7}, {%8,%9}, {%0,%1,%2,%3};"
        : "+f"(d[0]), "+f"(d[1]), "+f"(d[2]), "+f"(d[3])
        : "r"(a[0]), "r"(a[1]), "r"(a[2]), "r"(a[3]), "r"(b[0]), "r"(b[1]));
}

// pack two floats (x_lo = even k, x_hi = odd k) into bf16x2 hi/lo planes
__device__ __forceinline__ void bf16_split2(float x_lo, float x_hi,
                                            unsigned& hw, unsigned& lw)
{
    asm("cvt.rn.bf16x2.f32 %0, %1, %2;" : "=r"(hw) : "f"(x_hi), "f"(x_lo));
    float h_lo = __uint_as_float(hw << 16);
    float h_hi = __uint_as_float(hw & 0xffff0000u);
    asm("cvt.rn.bf16x2.f32 %0, %1, %2;" : "=r"(lw) : "f"(x_hi - h_hi), "f"(x_lo - h_lo));
}

// One 16-deep K slice, bf16x3: 2 m-tiles x 4 n-tiles of m16n8k16.
template<int SA, int SB>
__device__ __forceinline__ void do_mma16(const unsigned* AhP, const unsigned* AlP,
                                         const unsigned* BhP, const unsigned* BlP,
                                         int wm, int wn, int l4, int g,
                                         float acc[2][4][4])
{
    unsigned ah[2][4], al[2][4], bh[4][2], bl[4][2];
    const unsigned* r0 = AhP + l4 * SA;
    const unsigned* r1 = AhP + (l4 + 4) * SA;
    const unsigned* s0 = AlP + l4 * SA;
    const unsigned* s1 = AlP + (l4 + 4) * SA;
    #pragma unroll
    for (int mt = 0; mt < 2; mt++) {
        int mm = wm + mt * 16;
        ah[mt][0] = r0[mm + g];
        ah[mt][1] = r0[mm + g + 8];
        ah[mt][2] = r1[mm + g];
        ah[mt][3] = r1[mm + g + 8];
        al[mt][0] = s0[mm + g];
        al[mt][1] = s0[mm + g + 8];
        al[mt][2] = s1[mm + g];
        al[mt][3] = s1[mm + g + 8];
    }
    const unsigned* t0 = BhP + l4 * SB;
    const unsigned* t1 = BhP + (l4 + 4) * SB;
    const unsigned* u0 = BlP + l4 * SB;
    const unsigned* u1 = BlP + (l4 + 4) * SB;
    #pragma unroll
    for (int nt = 0; nt < 4; nt++) {
        int nn = wn + nt * 8 + g;
        bh[nt][0] = t0[nn];
        bh[nt][1] = t1[nn];
        bl[nt][0] = u0[nn];
        bl[nt][1] = u1[nn];
    }
    #pragma unroll
    for (int mt = 0; mt < 2; mt++)
        #pragma unroll
        for (int nt = 0; nt < 4; nt++) {
            mma_bf16(acc[mt][nt], ah[mt], bh[nt]);
            mma_bf16(acc[mt][nt], ah[mt], bl[nt]);
            mma_bf16(acc[mt][nt], al[mt], bh[nt]);
        }
}

// ---------------- LayerNorm over rows ----------------
__global__ void ln_kernel(const float* __restrict__ x,
                          const float* __restrict__ w,
                          const float* __restrict__ b,
                          float* __restrict__ y, int C)
{
    int row = blockIdx.x;
    const float* xr = x + (size_t)row * C;
    float s1 = 0.f, s2 = 0.f;
    for (int c = threadIdx.x; c < C; c += blockDim.x) {
        float v = xr[c]; s1 += v; s2 += v * v;
    }
    __shared__ float red[64];
    #pragma unroll
    for (int o = 16; o; o >>= 1) {
        s1 += __shfl_xor_sync(0xffffffffu, s1, o);
        s2 += __shfl_xor_sync(0xffffffffu, s2, o);
    }
    int wid = threadIdx.x >> 5, lid = threadIdx.x & 31;
    if (lid == 0) { red[wid] = s1; red[wid + 32] = s2; }
    __syncthreads();
    if (wid == 0) {
        s1 = (lid < (blockDim.x >> 5)) ? red[lid] : 0.f;
        s2 = (lid < (blockDim.x >> 5)) ? red[lid + 32] : 0.f;
        #pragma unroll
        for (int o = 16; o; o >>= 1) {
            s1 += __shfl_xor_sync(0xffffffffu, s1, o);
            s2 += __shfl_xor_sync(0xffffffffu, s2, o);
        }
        if (lid == 0) { red[0] = s1; red[1] = s2; }
    }
    __syncthreads();
    float mean = red[0] / C;
    float var  = red[1] / C - mean * mean;
    float rs   = rsqrtf(var + EPS);
    float* yr = y + (size_t)row * C;
    for (int c = threadIdx.x; c < C; c += blockDim.x) {
        float v = (xr[c] - mean) * rs;
        if (w) v = v * w[c] + b[c];
        yr[c] = v;
    }
}

// ---------------- bf16x3 tensor-core GEMM, batched over blockIdx.z --------
struct GemmJob { const float* A; const float* W; const float* bias;
                 const float* mul; float* out; int sig; };
struct GemmBatch { GemmJob j[4]; };

__global__ void __launch_bounds__(256)
gemm_tc_kernel(GemmBatch batch, int M, int N, int K)
{
    __shared__ unsigned Ah[2][8][136], Al[2][8][136];   // [kword][m]
    __shared__ unsigned Bh[2][8][72],  Bl[2][8][72];    // [kword][n]

    GemmJob jb = batch.j[blockIdx.z];
    const float* __restrict__ A = jb.A;
    const float* __restrict__ W = jb.W;

    int t = threadIdx.x;
    int m0 = blockIdx.y * 128, n0 = blockIdx.x * 64;
    int w = t >> 5, lane = t & 31;
    int wm = (w >> 1) * 32, wn = (w & 1) * 32;
    int l4 = lane & 3, g = lane >> 2;

    int am = t >> 1, awb = (t & 1) * 4;
    const float* Ap = A + (size_t)(m0 + am) * K + (t & 1) * 8;
    int bw = t >> 5, bn = (t & 31) * 2;
    const float* Wp0 = W + (size_t)(bw * 2)     * N + n0 + bn;
    const float* Wp1 = W + (size_t)(bw * 2 + 1) * N + n0 + bn;

    float acc[2][4][4] = {};
    int nkt = K >> 4;

    float4 a0 = *(const float4*)Ap;
    float4 a1 = *(const float4*)(Ap + 4);
    float2 bv0 = *(const float2*)Wp0;
    float2 bv1 = *(const float2*)Wp1;

    for (int kt = 0; kt < nkt; kt++) {
        int p = kt & 1;
        {
            float av[8] = {a0.x,a0.y,a0.z,a0.w,a1.x,a1.y,a1.z,a1.w};
            #pragma unroll
            for (int i = 0; i < 4; i++) {
                unsigned hw, lw;
                bf16_split2(av[2*i], av[2*i+1], hw, lw);
                Ah[p][awb + i][am] = hw;
                Al[p][awb + i][am] = lw;
            }
            unsigned h0, l0, h1, l1;
            bf16_split2(bv0.x, bv1.x, h0, l0);
            bf16_split2(bv0.y, bv1.y, h1, l1);
            *(uint2*)&Bh[p][bw][bn] = make_uint2(h0, h1);
            *(uint2*)&Bl[p][bw][bn] = make_uint2(l0, l1);
        }
        __syncthreads();
        if (kt + 1 < nkt) {
            const float* Ap2 = Ap + (size_t)(kt + 1) * 16;
            a0 = *(const float4*)Ap2;
            a1 = *(const float4*)(Ap2 + 4);
            bv0 = *(const float2*)(Wp0 + (size_t)(kt + 1) * 16 * N);
            bv1 = *(const float2*)(Wp1 + (size_t)(kt + 1) * 16 * N);
        }
        do_mma16<136, 72>(&Ah[p][0][0], &Al[p][0][0], &Bh[p][0][0], &Bl[p][0][0],
                          wm, wn, l4, g, acc);
    }

    const float* bias = jb.bias;
    const float* mul  = jb.mul;
    float* out = jb.out;
    int sig = jb.sig;
    #pragma unroll
    for (int mt = 0; mt < 2; mt++)
        #pragma unroll
        for (int nt = 0; nt < 4; nt++) {
            int n = n0 + wn + nt * 8 + l4 * 2;
            float bx = 0.f, by = 0.f;
            if (bias) { bx = bias[n]; by = bias[n + 1]; }
            #pragma unroll
            for (int half = 0; half < 2; half++) {
                int m = m0 + wm + mt * 16 + g + half * 8;
                float x = acc[mt][nt][half * 2]     + bx;
                float y = acc[mt][nt][half * 2 + 1] + by;
                if (sig) {
                    x = 1.f / (1.f + __expf(-x));
                    y = 1.f / (1.f + __expf(-y));
                }
                if (mul) {
                    float2 mv = *(const float2*)&mul[(size_t)m * N + n];
                    x *= mv.x; y *= mv.y;
                }
                *(float2*)&out[(size_t)m * N + n] = make_float2(x, y);
            }
        }
}

// ---------------- elementwise ----------------
__global__ void adaln_ew_kernel(const float* __restrict__ t1,
                                const float* __restrict__ t2,
                                const float* __restrict__ aln,
                                float* __restrict__ a2, int n)
{
    int i = blockIdx.x * blockDim.x + threadIdx.x;
    if (i < n) {
        float s = 1.f / (1.f + __expf(-t1[i]));
        a2[i] = s * aln[i] + t2[i];
    }
}

// ---------------- pair bias via bf16x3 mma (proven R15) -------------------
__global__ void __launch_bounds__(256)
pairbias_kernel(const float* __restrict__ z,
                const float* __restrict__ beta,
                const float* __restrict__ lnb_w,
                const float* __restrict__ lnb_b,
                const float* __restrict__ Wb,
                float* __restrict__ scores)
{
    __shared__ unsigned zh[64][68], zl[64][68];
    __shared__ unsigned wbh[16][68], wbl[16][68];
    __shared__ float ps1[64][33], ps2[64][33];
    __shared__ float bt[64*16];
    __shared__ float colsum[16], consth[16];
    __shared__ float mean_s[64], rs_s[64];
    __shared__ float pacc[64][17];

    int t  = threadIdx.x;
    int w  = t >> 5, lane = t & 31;
    int j0 = blockIdx.x * 64;
    int bi = blockIdx.y;
    int b  = bi / II, i = bi % II;

    {
        const float4* zg = (const float4*)(z + ((size_t)bi * II + j0) * CZ);
        #pragma unroll
        for (int it = 0; it < 8; it++) {
            int e = t + 256 * it;
            int r = e >> 5;
            float4 v = zg[(size_t)r * 32 + lane];
            unsigned hw0, lw0, hw1, lw1;
            bf16_split2(v.x, v.y, hw0, lw0);
            bf16_split2(v.z, v.w, hw1, lw1);
            *(uint2*)&zh[r][lane * 2] = make_uint2(hw0, hw1);
            *(uint2*)&zl[r][lane * 2] = make_uint2(lw0, lw1);
            ps1[r][lane] = v.x + v.y + v.z + v.w;
            ps2[r][lane] = v.x*v.x + v.y*v.y + v.z*v.z + v.w*v.w;
        }
    }
    {
        int h = t & 15, kb = (t >> 4) * 4;
        #pragma unroll
        for (int u = 0; u < 4; u++) {
            int c = (kb + u) * 2;
            float w0 = lnb_w[c]     * Wb[c * 16 + h];
            float w1 = lnb_w[c + 1] * Wb[(c + 1) * 16 + h];
            unsigned hw, lw;
            bf16_split2(w0, w1, hw, lw);
            wbh[h][kb + u] = hw;
            wbl[h][kb + u] = lw;
        }
    }
    {
        const float4* bg = (const float4*)(beta + ((size_t)bi * II + j0) * HH);
        float4 v = bg[t];
        int e = t * 4;
        int j = e >> 4, h = e & 15;
        bt[j*16 + ((h+0 + j) & 15)] = v.x;
        bt[j*16 + ((h+1 + j) & 15)] = v.y;
        bt[j*16 + ((h+2 + j) & 15)] = v.z;
        bt[j*16 + ((h+3 + j) & 15)] = v.w;
    }
    if (t < 16) {
        float cs = 0.f, ch = 0.f;
        for (int c = 0; c < 128; c++) {
            cs += lnb_w[c] * Wb[c * 16 + t];
            ch += lnb_b[c] * Wb[c * 16 + t];
        }
        colsum[t] = cs; consth[t] = ch;
    }
    __syncthreads();

    if (t < 64) {
        float a = 0.f, b2 = 0.f;
        #pragma unroll
        for (int l = 0; l < 32; l++) { a += ps1[t][l]; b2 += ps2[t][l]; }
        float m  = a * (1.f / 128.f);
        float var = b2 * (1.f / 128.f) - m * m;
        mean_s[t] = m;
        rs_s[t]   = rsqrtf(var + EPS);
    }

    int g2 = lane >> 2, l4 = lane & 3;
    int wm = (w >> 1) * 16, wn = (w & 1) * 8;
    float acc[4] = {0.f, 0.f, 0.f, 0.f};
    const unsigned* zh0 = &zh[wm + g2][0];
    const unsigned* zh1 = &zh[wm + g2 + 8][0];
    const unsigned* zl0 = &zl[wm + g2][0];
    const unsigned* zl1 = &zl[wm + g2 + 8][0];
    const unsigned* wh0 = &wbh[wn + g2][0];
    const unsigned* wl0 = &wbl[wn + g2][0];
    #pragma unroll
    for (int kt = 0; kt < 8; kt++) {
        int kb = kt * 8;
        unsigned ah[4], al[4], bh2[2], bl2[2];
        ah[0] = zh0[kb + l4];
        ah[1] = zh1[kb + l4];
        ah[2] = zh0[kb + l4 + 4];
        ah[3] = zh1[kb + l4 + 4];
        al[0] = zl0[kb + l4];
        al[1] = zl1[kb + l4];
        al[2] = zl0[kb + l4 + 4];
        al[3] = zl1[kb + l4 + 4];
        bh2[0] = wh0[kb + l4];
        bh2[1] = wh0[kb + l4 + 4];
        bl2[0] = wl0[kb + l4];
        bl2[1] = wl0[kb + l4 + 4];
        mma_bf16(acc, ah, bh2);
        mma_bf16(acc, ah, bl2);
        mma_bf16(acc, al, bh2);
    }

    pacc[wm + g2][wn + 2 * l4]         = acc[0];
    pacc[wm + g2][wn + 2 * l4 + 1]     = acc[1];
    pacc[wm + g2 + 8][wn + 2 * l4]     = acc[2];
    pacc[wm + g2 + 8][wn + 2 * l4 + 1] = acc[3];
    __syncthreads();

    {
        int j = t & 63, hb = t >> 6;
        float mean = mean_s[j], rs = rs_s[j];
        #pragma unroll
        for (int u = 0; u < 4; u++) {
            int h = hb * 4 + u;
            float v = pacc[j][h];
            v = rs * (v - mean * colsum[h]) + consth[h] + bt[j*16 + ((h + j) & 15)];
            scores[(((size_t)(b*16 + h)) * II + i) * II + j0 + j] = v;
        }
    }
}

// ---------------- fused attention: qk (bf16x3 mma) + softmax + AV + gate --
// grid: (II/16, B*H). 256 threads = 8 warps. Block owns 16 i-rows of one (b,h).
__global__ void __launch_bounds__(256)
attn_kernel(const float* __restrict__ scores,
            const float* __restrict__ q,
            const float* __restrict__ k,
            const float* __restrict__ v,
            const float* __restrict__ gbuf,
            float* __restrict__ o)
{
    __shared__ __align__(16) float p[16][772];           // 49.4KB, stride≡4 mod 32
    __shared__ __align__(16) unsigned kplane[2][24][76]; // k hi/lo, 14.6KB (aliased by vt)
    __shared__ unsigned qh[24][20], ql[24][20];          // q planes, 3.8KB
    __shared__ float inv_s[16];

    float* vt = (float*)kplane;                          // [48][68] alias for AV phase

    int bh = blockIdx.y, b = bh >> 4, h = bh & 15;
    int ibase = blockIdx.x * 16;
    int t = threadIdx.x, warp = t >> 5, lane = t & 31;
    int g = lane >> 2, l4 = lane & 3;

    // 1) preload bias strip into p (coalesced float4)
    {
        const float4* src = (const float4*)(scores + (((size_t)bh * II) + ibase) * II);
        for (int e = t; e < 16 * 192; e += 256) {
            int r = e / 192, c4 = e % 192;
            *(float4*)&p[r][c4 * 4] = src[(size_t)r * 192 + c4];
        }
    }
    // 2) stage q planes (split once)
    if (t < 192) {
        int r = t / 12, dq = t % 12;
        float4 vq = *(const float4*)&q[(((size_t)b * II + ibase + r) * HH + h) * DD + dq * 4];
        unsigned hw0, lw0, hw1, lw1;
        bf16_split2(vq.x, vq.y, hw0, lw0);
        bf16_split2(vq.z, vq.w, hw1, lw1);
        qh[dq*2][r]   = hw0; ql[dq*2][r]   = lw0;
        qh[dq*2+1][r] = hw1; ql[dq*2+1][r] = lw1;
    }
    __syncthreads();

    // 3) q fragments register-resident for all 3 k16-tiles
    unsigned uah[3][4], ual[3][4];
    #pragma unroll
    for (int kt = 0; kt < 3; kt++) {
        int kb = kt * 8;
        uah[kt][0] = qh[kb + l4][g];
        uah[kt][1] = qh[kb + l4][g + 8];
        uah[kt][2] = qh[kb + l4 + 4][g];
        uah[kt][3] = qh[kb + l4 + 4][g + 8];
        ual[kt][0] = ql[kb + l4][g];
        ual[kt][1] = ql[kb + l4][g + 8];
        ual[kt][2] = ql[kb + l4 + 4][g];
        ual[kt][3] = ql[kb + l4 + 4][g + 8];
    }

    const float sc = rsqrtf(48.f);

    // 4) qk: 12 chunks of 64 j; p[i][j] += (q.k)*sc
    for (int jt = 0; jt < II / 64; jt++) {
        int j0 = jt * 64;
        {   // stage k chunk to bf16 planes (split once; conflict-free stride 76)
            int r = t >> 2, seg = t & 3;
            const float* kp = &k[(((size_t)b * II + j0 + r) * HH + h) * DD + seg * 12];
            #pragma unroll
            for (int u = 0; u < 3; u++) {
                float4 vk = *(const float4*)(kp + u * 4);
                int kw = seg * 6 + u * 2;
                unsigned hw0, lw0, hw1, lw1;
                bf16_split2(vk.x, vk.y, hw0, lw0);
                bf16_split2(vk.z, vk.w, hw1, lw1);
                kplane[0][kw][r]     = hw0; kplane[1][kw][r]     = lw0;
                kplane[0][kw + 1][r] = hw1; kplane[1][kw + 1][r] = lw1;
            }
        }
        __syncthreads();
        float acc[4] = {0.f, 0.f, 0.f, 0.f};
        int nn = warp * 8 + g;
        #pragma unroll
        for (int kt = 0; kt < 3; kt++) {
            int kb = kt * 8;
            unsigned bh2[2], bl2[2];
            bh2[0] = kplane[0][kb + l4][nn];
            bh2[1] = kplane[0][kb + l4 + 4][nn];
            bl2[0] = kplane[1][kb + l4][nn];
            bl2[1] = kplane[1][kb + l4 + 4][nn];
            mma_bf16(acc, uah[kt], bh2);
            mma_bf16(acc, uah[kt], bl2);
            mma_bf16(acc, ual[kt], bh2);
        }
        int jc = j0 + warp * 8 + 2 * l4;
        p[g][jc]         += acc[0] * sc;
        p[g][jc + 1]     += acc[1] * sc;
        p[g + 8][jc]     += acc[2] * sc;
        p[g + 8][jc + 1] += acc[3] * sc;
        __syncthreads();   // all mma reads of kplane done before next restage
    }

    // 5) softmax (unnormalized exp; 1/sum deferred to epilogue)
    for (int r = warp; r < 16; r += 8) {
        float mx = -1e30f;
        for (int j = lane; j < II; j += 32) mx = fmaxf(mx, p[r][j]);
        #pragma unroll
        for (int off = 16; off; off >>= 1) mx = fmaxf(mx, __shfl_xor_sync(0xffffffffu, mx, off));
        float sum = 0.f;
        for (int j = lane; j < II; j += 32) {
            float e = __expf(p[r][j] - mx); p[r][j] = e; sum += e;
        }
        #pragma unroll
        for (int off = 16; off; off >>= 1) sum += __shfl_xor_sync(0xffffffffu, sum, off);
        if (lane == 0) inv_s[r] = 1.f / sum;
    }
    __syncthreads();

    // 6) AV: o[i,d] = sum_j p[i][j]*v[j][d]; 64-wide v tiles in aliased smem
    int ia = t / 24, d0 = t % 24;          // valid for t<192
    float acc2[2][2] = {};
    for (int jt = 0; jt < II / 64; jt++) {
        for (int e = t; e < 64 * 48; e += 256) {
            int jj = e / 48, d = e % 48;
            vt[d * 68 + jj] = v[(((size_t)b * II + jt * 64 + jj) * HH + h) * DD + d];
        }
        __syncthreads();
        if (t < 192) {
            #pragma unroll
            for (int jj = 0; jj < 64; jj += 4) {
                float4 p0 = *(const float4*)&p[ia][jt * 64 + jj];
                float4 p1 = *(const float4*)&p[ia + 8][jt * 64 + jj];
                float4 v0 = *(const float4*)&vt[d0 * 68 + jj];
                float4 v1 = *(const float4*)&vt[(d0 + 24) * 68 + jj];
                acc2[0][0] += p0.x*v0.x + p0.y*v0.y + p0.z*v0.z + p0.w*v0.w;
                acc2[0][1] += p0.x*v1.x + p0.y*v1.y + p0.z*v1.z + p0.w*v1.w;
                acc2[1][0] += p1.x*v0.x + p1.y*v0.y + p1.z*v0.z + p1.w*v0.w;
                acc2[1][1] += p1.x*v1.x + p1.y*v1.y + p1.z*v1.z + p1.w*v1.w;
            }
        }
        __syncthreads();
    }
    if (t < 192) {
        #pragma unroll
        for (int u = 0; u < 2; u++)
            #pragma unroll
            for (int w2 = 0; w2 < 2; w2++) {
                int i = ibase + ia + u * 8;
                int d = d0 + w2 * 24;
                float iv = inv_s[ia + u * 8];
                size_t gi = (((size_t)b * II + i) * HH + h) * DD + d;
                float gt = 1.f / (1.f + __expf(-gbuf[gi]));
                o[gi] = acc2[u][w2] * iv * gt;
            }
    }
}

// ---------------- host launch ----------------
static float* sym(const void* s) {
    void* p = nullptr;
    cudaGetSymbolAddress(&p, s);
    return (float*)p;
}

extern "C" void kernel_launch(void* const* d_in, const int* in_sizes, int n_in,
                              void* d_out, int out_size)
{
    const float* a_i      = (const float*)d_in[0];
    const float* s_i      = (const float*)d_in[1];
    const float* z_ij     = (const float*)d_in[2];
    const float* beta_ij  = (const float*)d_in[3];
    const float* lns_w    = (const float*)d_in[4];
    const float* lns_b    = (const float*)d_in[5];
    const float* Ws       = (const float*)d_in[6];
    const float* bs       = (const float*)d_in[7];
    const float* Wnb      = (const float*)d_in[8];
    const float* Wq       = (const float*)d_in[9];
    const float* bq       = (const float*)d_in[10];
    const float* Wk       = (const float*)d_in[11];
    const float* Wv       = (const float*)d_in[12];
    const float* lnb_w    = (const float*)d_in[13];
    const float* lnb_b    = (const float*)d_in[14];
    const float* Wb       = (const float*)d_in[15];
    const float* Wg       = (const float*)d_in[16];
    const float* Wo       = (const float*)d_in[17];
    const float* Ws_out   = (const float*)d_in[18];
    const float* bs_out   = (const float*)d_in[19];
    float* out = (float*)d_out;

    float* p_aln  = sym(g_aln);
    float* p_sln  = sym(g_sln);
    float* p_t1   = sym(g_t1);
    float* p_t2   = sym(g_t2);
    float* p_a2   = sym(g_a2);
    float* p_q    = sym(g_q);
    float* p_k    = sym(g_k);
    float* p_v    = sym(g_v);
    float* p_g    = sym(g_gbuf);
    float* p_gate = sym(g_gate);
    float* p_sc   = sym(g_scores);
    float* p_o    = sym(g_o);

    const int NEL = ROWS * CA;

    // pair bias first (independent of everything else)
    {
        dim3 g(II / 64, ROWS);
        pairbias_kernel<<<g, 256>>>(z_ij, beta_ij, lnb_w, lnb_b, Wb, p_sc);
    }

    // LayerNorms
    ln_kernel<<<ROWS, 256>>>(a_i, nullptr, nullptr, p_aln, CA);
    ln_kernel<<<ROWS, 256>>>(s_i, lns_w, lns_b, p_sln, CS);

    // AdaLN pair + output gate, all K=384, one batched launch
    {
        GemmBatch gb = {};
        gb.j[0] = { p_sln, Ws,     bs,      nullptr, p_t1,   0 };
        gb.j[1] = { p_sln, Wnb,    nullptr, nullptr, p_t2,   0 };
        gb.j[2] = { s_i,   Ws_out, bs_out,  nullptr, p_gate, 1 };
        dim3 g(CA / 64, ROWS / 128, 3);
        gemm_tc_kernel<<<g, 256>>>(gb, ROWS, CA, CS);
    }
    adaln_ew_kernel<<<(NEL + 255) / 256, 256>>>(p_t1, p_t2, p_aln, p_a2, NEL);

    // projections q,k,v,g (K=768)
    {
        GemmBatch gb = {};
        gb.j[0] = { p_a2, Wq, bq,      nullptr, p_q, 0 };
        gb.j[1] = { p_a2, Wk, nullptr, nullptr, p_k, 0 };
        gb.j[2] = { p_a2, Wv, nullptr, nullptr, p_v, 0 };
        gb.j[3] = { p_a2, Wg, nullptr, nullptr, p_g, 0 };
        dim3 g(HC / 64, ROWS / 128, 4);
        gemm_tc_kernel<<<g, 256>>>(gb, ROWS, HC, CA);
    }

    // fused attention: qk + bias + softmax + AV + gate (scores read once)
    {
        dim3 g(II / 16, BB * HH);
        attn_kernel<<<g, 256>>>(p_sc, p_q, p_k, p_v, p_g, p_o);
    }

    // out = gate * (o @ Wo)
    {
        GemmBatch gb = {};
        gb.j[0] = { p_o, Wo, nullptr, p_gate, out, 0 };
        dim3 g(CA / 64, ROWS / 128, 1);
        gemm_tc_kernel<<<g, 256>>>(gb, ROWS, CA, HC);
    }
}

// round 17
// speedup vs baseline: 1.0200x; 1.0200x over previous
#include <cuda_runtime.h>
#include <cuda_bf16.h>
#include <math.h>

// Problem constants
#define BB 2
#define II 768
#define CA 768
#define CS 384
#define CZ 128
#define HH 16
#define DD 48
#define HC 768
#define ROWS (BB*II)          // 1536
#define EPS 1e-5f

// ---------------- device scratch (no allocations allowed) ----------------
__device__ float g_aln  [ROWS*CA];
__device__ float g_sln  [ROWS*CS];
__device__ float g_t1   [ROWS*CA];
__device__ float g_t2   [ROWS*CA];
__device__ float g_a2   [ROWS*CA];
__device__ float g_q    [ROWS*HC];
__device__ float g_k    [ROWS*HC];
__device__ float g_v    [ROWS*HC];
__device__ float g_gbuf [ROWS*HC];
__device__ float g_gate [ROWS*CA];
__device__ float g_scores[(size_t)BB*HH*II*II];   // [b][h][i][j]  ~75.5 MB
__device__ float g_o    [ROWS*HC];

// ---------------- bf16 helpers ----------------
__device__ __forceinline__ void mma_bf16(float* d, const unsigned* a, const unsigned* b) {
    asm volatile(
        "mma.sync.aligned.m16n8k16.row.col.f32.bf16.bf16.f32 "
        "{%0,%1,%2,%3}, {%4,%5,%6,%7}, {%8,%9}, {%0,%1,%2,%3};"
        : "+f"(d[0]), "+f"(d[1]), "+f"(d[2]), "+f"(d[3])
        : "r"(a[0]), "r"(a[1]), "r"(a[2]), "r"(a[3]), "r"(b[0]), "r"(b[1]));
}

// pack two floats (x_lo = even k, x_hi = odd k) into bf16x2 hi/lo planes
__device__ __forceinline__ void bf16_split2(float x_lo, float x_hi,
                                            unsigned& hw, unsigned& lw)
{
    asm("cvt.rn.bf16x2.f32 %0, %1, %2;" : "=r"(hw) : "f"(x_hi), "f"(x_lo));
    float h_lo = __uint_as_float(hw << 16);
    float h_hi = __uint_as_float(hw & 0xffff0000u);
    asm("cvt.rn.bf16x2.f32 %0, %1, %2;" : "=r"(lw) : "f"(x_hi - h_hi), "f"(x_lo - h_lo));
}

// One 16-deep K slice, bf16x3: 2 m-tiles x 4 n-tiles of m16n8k16.
// A plane layout [kword(8)][m], B plane [kword(8)][n].
template<int SA, int SB>
__device__ __forceinline__ void do_mma16(const unsigned* AhP, const unsigned* AlP,
                                         const unsigned* BhP, const unsigned* BlP,
                                         int wm, int wn, int l4, int g,
                                         float acc[2][4][4])
{
    unsigned ah[2][4], al[2][4], bh[4][2], bl[4][2];
    const unsigned* r0 = AhP + l4 * SA;
    const unsigned* r1 = AhP + (l4 + 4) * SA;
    const unsigned* s0 = AlP + l4 * SA;
    const unsigned* s1 = AlP + (l4 + 4) * SA;
    #pragma unroll
    for (int mt = 0; mt < 2; mt++) {
        int mm = wm + mt * 16;
        ah[mt][0] = r0[mm + g];
        ah[mt][1] = r0[mm + g + 8];
        ah[mt][2] = r1[mm + g];
        ah[mt][3] = r1[mm + g + 8];
        al[mt][0] = s0[mm + g];
        al[mt][1] = s0[mm + g + 8];
        al[mt][2] = s1[mm + g];
        al[mt][3] = s1[mm + g + 8];
    }
    const unsigned* t0 = BhP + l4 * SB;
    const unsigned* t1 = BhP + (l4 + 4) * SB;
    const unsigned* u0 = BlP + l4 * SB;
    const unsigned* u1 = BlP + (l4 + 4) * SB;
    #pragma unroll
    for (int nt = 0; nt < 4; nt++) {
        int nn = wn + nt * 8 + g;
        bh[nt][0] = t0[nn];
        bh[nt][1] = t1[nn];
        bl[nt][0] = u0[nn];
        bl[nt][1] = u1[nn];
    }
    #pragma unroll
    for (int mt = 0; mt < 2; mt++)
        #pragma unroll
        for (int nt = 0; nt < 4; nt++) {
            mma_bf16(acc[mt][nt], ah[mt], bh[nt]);
            mma_bf16(acc[mt][nt], ah[mt], bl[nt]);
            mma_bf16(acc[mt][nt], al[mt], bh[nt]);
        }
}

// ---------------- LayerNorm over rows ----------------
__global__ void ln_kernel(const float* __restrict__ x,
                          const float* __restrict__ w,
                          const float* __restrict__ b,
                          float* __restrict__ y, int C)
{
    int row = blockIdx.x;
    const float* xr = x + (size_t)row * C;
    float s1 = 0.f, s2 = 0.f;
    for (int c = threadIdx.x; c < C; c += blockDim.x) {
        float v = xr[c]; s1 += v; s2 += v * v;
    }
    __shared__ float red[64];
    #pragma unroll
    for (int o = 16; o; o >>= 1) {
        s1 += __shfl_xor_sync(0xffffffffu, s1, o);
        s2 += __shfl_xor_sync(0xffffffffu, s2, o);
    }
    int wid = threadIdx.x >> 5, lid = threadIdx.x & 31;
    if (lid == 0) { red[wid] = s1; red[wid + 32] = s2; }
    __syncthreads();
    if (wid == 0) {
        s1 = (lid < (blockDim.x >> 5)) ? red[lid] : 0.f;
        s2 = (lid < (blockDim.x >> 5)) ? red[lid + 32] : 0.f;
        #pragma unroll
        for (int o = 16; o; o >>= 1) {
            s1 += __shfl_xor_sync(0xffffffffu, s1, o);
            s2 += __shfl_xor_sync(0xffffffffu, s2, o);
        }
        if (lid == 0) { red[0] = s1; red[1] = s2; }
    }
    __syncthreads();
    float mean = red[0] / C;
    float var  = red[1] / C - mean * mean;
    float rs   = rsqrtf(var + EPS);
    float* yr = y + (size_t)row * C;
    for (int c = threadIdx.x; c < C; c += blockDim.x) {
        float v = (xr[c] - mean) * rs;
        if (w) v = v * w[c] + b[c];
        yr[c] = v;
    }
}

// ---------------- bf16x3 tensor-core GEMM, batched over blockIdx.z --------
struct GemmJob { const float* A; const float* W; const float* bias;
                 const float* mul; float* out; int sig; };
struct GemmBatch { GemmJob j[4]; };

__global__ void __launch_bounds__(256)
gemm_tc_kernel(GemmBatch batch, int M, int N, int K)
{
    __shared__ unsigned Ah[2][8][136], Al[2][8][136];   // [kword][m]
    __shared__ unsigned Bh[2][8][72],  Bl[2][8][72];    // [kword][n]

    GemmJob jb = batch.j[blockIdx.z];
    const float* __restrict__ A = jb.A;
    const float* __restrict__ W = jb.W;

    int t = threadIdx.x;
    int m0 = blockIdx.y * 128, n0 = blockIdx.x * 64;
    int w = t >> 5, lane = t & 31;
    int wm = (w >> 1) * 32, wn = (w & 1) * 32;
    int l4 = lane & 3, g = lane >> 2;

    int am = t >> 1, awb = (t & 1) * 4;
    const float* Ap = A + (size_t)(m0 + am) * K + (t & 1) * 8;
    int bw = t >> 5, bn = (t & 31) * 2;
    const float* Wp0 = W + (size_t)(bw * 2)     * N + n0 + bn;
    const float* Wp1 = W + (size_t)(bw * 2 + 1) * N + n0 + bn;

    float acc[2][4][4] = {};
    int nkt = K >> 4;

    float4 a0 = *(const float4*)Ap;
    float4 a1 = *(const float4*)(Ap + 4);
    float2 bv0 = *(const float2*)Wp0;
    float2 bv1 = *(const float2*)Wp1;

    for (int kt = 0; kt < nkt; kt++) {
        int p = kt & 1;
        {
            float av[8] = {a0.x,a0.y,a0.z,a0.w,a1.x,a1.y,a1.z,a1.w};
            #pragma unroll
            for (int i = 0; i < 4; i++) {
                unsigned hw, lw;
                bf16_split2(av[2*i], av[2*i+1], hw, lw);
                Ah[p][awb + i][am] = hw;
                Al[p][awb + i][am] = lw;
            }
            unsigned h0, l0, h1, l1;
            bf16_split2(bv0.x, bv1.x, h0, l0);
            bf16_split2(bv0.y, bv1.y, h1, l1);
            *(uint2*)&Bh[p][bw][bn] = make_uint2(h0, h1);
            *(uint2*)&Bl[p][bw][bn] = make_uint2(l0, l1);
        }
        __syncthreads();
        if (kt + 1 < nkt) {
            const float* Ap2 = Ap + (size_t)(kt + 1) * 16;
            a0 = *(const float4*)Ap2;
            a1 = *(const float4*)(Ap2 + 4);
            bv0 = *(const float2*)(Wp0 + (size_t)(kt + 1) * 16 * N);
            bv1 = *(const float2*)(Wp1 + (size_t)(kt + 1) * 16 * N);
        }
        do_mma16<136, 72>(&Ah[p][0][0], &Al[p][0][0], &Bh[p][0][0], &Bl[p][0][0],
                          wm, wn, l4, g, acc);
    }

    const float* bias = jb.bias;
    const float* mul  = jb.mul;
    float* out = jb.out;
    int sig = jb.sig;
    #pragma unroll
    for (int mt = 0; mt < 2; mt++)
        #pragma unroll
        for (int nt = 0; nt < 4; nt++) {
            int n = n0 + wn + nt * 8 + l4 * 2;
            float bx = 0.f, by = 0.f;
            if (bias) { bx = bias[n]; by = bias[n + 1]; }
            #pragma unroll
            for (int half = 0; half < 2; half++) {
                int m = m0 + wm + mt * 16 + g + half * 8;
                float x = acc[mt][nt][half * 2]     + bx;
                float y = acc[mt][nt][half * 2 + 1] + by;
                if (sig) {
                    x = 1.f / (1.f + __expf(-x));
                    y = 1.f / (1.f + __expf(-y));
                }
                if (mul) {
                    float2 mv = *(const float2*)&mul[(size_t)m * N + n];
                    x *= mv.x; y *= mv.y;
                }
                *(float2*)&out[(size_t)m * N + n] = make_float2(x, y);
            }
        }
}

// ---------------- elementwise ----------------
__global__ void adaln_ew_kernel(const float* __restrict__ t1,
                                const float* __restrict__ t2,
                                const float* __restrict__ aln,
                                float* __restrict__ a2, int n)
{
    int i = blockIdx.x * blockDim.x + threadIdx.x;
    if (i < n) {
        float s = 1.f / (1.f + __expf(-t1[i]));
        a2[i] = s * aln[i] + t2[i];
    }
}

// ---------------- pair bias via bf16x3 mma (proven R15) -------------------
__global__ void __launch_bounds__(256)
pairbias_kernel(const float* __restrict__ z,
                const float* __restrict__ beta,
                const float* __restrict__ lnb_w,
                const float* __restrict__ lnb_b,
                const float* __restrict__ Wb,
                float* __restrict__ scores)
{
    __shared__ unsigned zh[64][68], zl[64][68];
    __shared__ unsigned wbh[16][68], wbl[16][68];
    __shared__ float ps1[64][33], ps2[64][33];
    __shared__ float bt[64*16];
    __shared__ float colsum[16], consth[16];
    __shared__ float mean_s[64], rs_s[64];
    __shared__ float pacc[64][17];

    int t  = threadIdx.x;
    int w  = t >> 5, lane = t & 31;
    int j0 = blockIdx.x * 64;
    int bi = blockIdx.y;
    int b  = bi / II, i = bi % II;

    {
        const float4* zg = (const float4*)(z + ((size_t)bi * II + j0) * CZ);
        #pragma unroll
        for (int it = 0; it < 8; it++) {
            int e = t + 256 * it;
            int r = e >> 5;
            float4 v = zg[(size_t)r * 32 + lane];
            unsigned hw0, lw0, hw1, lw1;
            bf16_split2(v.x, v.y, hw0, lw0);
            bf16_split2(v.z, v.w, hw1, lw1);
            *(uint2*)&zh[r][lane * 2] = make_uint2(hw0, hw1);
            *(uint2*)&zl[r][lane * 2] = make_uint2(lw0, lw1);
            ps1[r][lane] = v.x + v.y + v.z + v.w;
            ps2[r][lane] = v.x*v.x + v.y*v.y + v.z*v.z + v.w*v.w;
        }
    }
    {
        int h = t & 15, kb = (t >> 4) * 4;
        #pragma unroll
        for (int u = 0; u < 4; u++) {
            int c = (kb + u) * 2;
            float w0 = lnb_w[c]     * Wb[c * 16 + h];
            float w1 = lnb_w[c + 1] * Wb[(c + 1) * 16 + h];
            unsigned hw, lw;
            bf16_split2(w0, w1, hw, lw);
            wbh[h][kb + u] = hw;
            wbl[h][kb + u] = lw;
        }
    }
    {
        const float4* bg = (const float4*)(beta + ((size_t)bi * II + j0) * HH);
        float4 v = bg[t];
        int e = t * 4;
        int j = e >> 4, h = e & 15;
        bt[j*16 + ((h+0 + j) & 15)] = v.x;
        bt[j*16 + ((h+1 + j) & 15)] = v.y;
        bt[j*16 + ((h+2 + j) & 15)] = v.z;
        bt[j*16 + ((h+3 + j) & 15)] = v.w;
    }
    if (t < 16) {
        float cs = 0.f, ch = 0.f;
        for (int c = 0; c < 128; c++) {
            cs += lnb_w[c] * Wb[c * 16 + t];
            ch += lnb_b[c] * Wb[c * 16 + t];
        }
        colsum[t] = cs; consth[t] = ch;
    }
    __syncthreads();

    if (t < 64) {
        float a = 0.f, b2 = 0.f;
        #pragma unroll
        for (int l = 0; l < 32; l++) { a += ps1[t][l]; b2 += ps2[t][l]; }
        float m  = a * (1.f / 128.f);
        float var = b2 * (1.f / 128.f) - m * m;
        mean_s[t] = m;
        rs_s[t]   = rsqrtf(var + EPS);
    }

    int g2 = lane >> 2, l4 = lane & 3;
    int wm = (w >> 1) * 16, wn = (w & 1) * 8;
    float acc[4] = {0.f, 0.f, 0.f, 0.f};
    const unsigned* zh0 = &zh[wm + g2][0];
    const unsigned* zh1 = &zh[wm + g2 + 8][0];
    const unsigned* zl0 = &zl[wm + g2][0];
    const unsigned* zl1 = &zl[wm + g2 + 8][0];
    const unsigned* wh0 = &wbh[wn + g2][0];
    const unsigned* wl0 = &wbl[wn + g2][0];
    #pragma unroll
    for (int kt = 0; kt < 8; kt++) {
        int kb = kt * 8;
        unsigned ah[4], al[4], bh2[2], bl2[2];
        ah[0] = zh0[kb + l4];
        ah[1] = zh1[kb + l4];
        ah[2] = zh0[kb + l4 + 4];
        ah[3] = zh1[kb + l4 + 4];
        al[0] = zl0[kb + l4];
        al[1] = zl1[kb + l4];
        al[2] = zl0[kb + l4 + 4];
        al[3] = zl1[kb + l4 + 4];
        bh2[0] = wh0[kb + l4];
        bh2[1] = wh0[kb + l4 + 4];
        bl2[0] = wl0[kb + l4];
        bl2[1] = wl0[kb + l4 + 4];
        mma_bf16(acc, ah, bh2);
        mma_bf16(acc, ah, bl2);
        mma_bf16(acc, al, bh2);
    }

    pacc[wm + g2][wn + 2 * l4]         = acc[0];
    pacc[wm + g2][wn + 2 * l4 + 1]     = acc[1];
    pacc[wm + g2 + 8][wn + 2 * l4]     = acc[2];
    pacc[wm + g2 + 8][wn + 2 * l4 + 1] = acc[3];
    __syncthreads();

    {
        int j = t & 63, hb = t >> 6;
        float mean = mean_s[j], rs = rs_s[j];
        #pragma unroll
        for (int u = 0; u < 4; u++) {
            int h = hb * 4 + u;
            float v = pacc[j][h];
            v = rs * (v - mean * colsum[h]) + consth[h] + bt[j*16 + ((h + j) & 15)];
            scores[(((size_t)(b*16 + h)) * II + i) * II + j0 + j] = v;
        }
    }
}

// ---------------- scores += q.k/sqrt(D), bf16x3 tensor-core ----------------
// Block: 128 threads (4 warps, 2x2), 64x64 tile, K=48 staged once (3 k16-tiles).
__global__ void __launch_bounds__(128)
qk_tc_kernel(const float* __restrict__ q, const float* __restrict__ k,
             float* __restrict__ scores)
{
    __shared__ unsigned Qh[24][72], Ql[24][72], Kh[24][72], Kl[24][72]; // 27.6KB
    int bh = blockIdx.z, b = bh >> 4, h = bh & 15;
    int i0 = blockIdx.y * 64, j0 = blockIdx.x * 64;
    int t = threadIdx.x, w = t >> 5, lane = t & 31;
    int wm = (w >> 1) * 32, wn = (w & 1) * 32;
    int l4 = lane & 3, g = lane >> 2;

    // stage all K=48 at once: t covers row (t&63) of q (t<64... which = t>>6)
    // 128 threads: which = t >> 6 (0 = q rows, 1 = k rows)
    {
        int row = t & 63, which = t >> 6;
        const float* src = (which ? k : q)
            + (((size_t)b * II + (which ? j0 : i0) + row) * HH + h) * DD;
        unsigned (*Sh)[72] = which ? Kh : Qh;
        unsigned (*Sl)[72] = which ? Kl : Ql;
        #pragma unroll
        for (int u = 0; u < 12; u++) {
            float4 v = *(const float4*)(src + u * 4);
            unsigned hw0, lw0, hw1, lw1;
            bf16_split2(v.x, v.y, hw0, lw0);
            bf16_split2(v.z, v.w, hw1, lw1);
            Sh[u*2][row]   = hw0; Sl[u*2][row]   = lw0;
            Sh[u*2+1][row] = hw1; Sl[u*2+1][row] = lw1;
        }
    }
    __syncthreads();

    float acc[2][4][4] = {};
    #pragma unroll
    for (int kt = 0; kt < 3; kt++) {
        do_mma16<72, 72>(&Qh[kt*8][0], &Ql[kt*8][0], &Kh[kt*8][0], &Kl[kt*8][0],
                         wm, wn, l4, g, acc);
    }

    const float sc = rsqrtf(48.f);
    #pragma unroll
    for (int mt = 0; mt < 2; mt++)
        #pragma unroll
        for (int nt = 0; nt < 4; nt++)
            #pragma unroll
            for (int half = 0; half < 2; half++) {
                int i = i0 + wm + mt * 16 + g + half * 8;
                int jj = j0 + wn + nt * 8 + l4 * 2;
                size_t idx = ((size_t)bh * II + i) * II + jj;
                float2 old = *(float2*)&scores[idx];
                old.x += acc[mt][nt][half * 2]     * sc;
                old.y += acc[mt][nt][half * 2 + 1] * sc;
                *(float2*)&scores[idx] = old;
            }
}

// ---------------- softmax over j + AV + gate (scalar, proven) -------------
__global__ void __launch_bounds__(192)
softmax_av_kernel(const float* __restrict__ scores,
                  const float* __restrict__ v,
                  const float* __restrict__ gbuf,
                  float* __restrict__ o)
{
    __shared__ __align__(16) float p[16][II];    // 48KB
    __shared__ __align__(16) float vt[48][36];   // [d][j] transposed
    int bh = blockIdx.y, b = bh >> 4, h = bh & 15;
    int ibase = blockIdx.x * 16;
    int t = threadIdx.x, warp = t >> 5, lane = t & 31;

    for (int r = warp; r < 16; r += 6) {
        const float* srow = &scores[(((size_t)bh * II) + ibase + r) * II];
        float mx = -1e30f;
        for (int j = lane; j < II; j += 32) {
            float s = srow[j]; p[r][j] = s; mx = fmaxf(mx, s);
        }
        #pragma unroll
        for (int off = 16; off; off >>= 1) mx = fmaxf(mx, __shfl_xor_sync(0xffffffffu, mx, off));
        float sum = 0.f;
        for (int j = lane; j < II; j += 32) {
            float e = __expf(p[r][j] - mx); p[r][j] = e; sum += e;
        }
        #pragma unroll
        for (int off = 16; off; off >>= 1) sum += __shfl_xor_sync(0xffffffffu, sum, off);
        float inv = 1.f / sum;
        for (int j = lane; j < II; j += 32) p[r][j] *= inv;
    }
    __syncthreads();

    int ia = t / 24, d0 = t % 24;
    float acc[2][2] = {};
    for (int jt = 0; jt < II / 32; jt++) {
        for (int e = t; e < 32 * 48; e += 192) {
            int jj = e / 48, d = e % 48;
            vt[d][jj] = v[(((size_t)b * II + jt * 32 + jj) * HH + h) * DD + d];
        }
        __syncthreads();
        #pragma unroll
        for (int jj = 0; jj < 32; jj += 4) {
            float4 p0 = *(const float4*)&p[ia][jt * 32 + jj];
            float4 p1 = *(const float4*)&p[ia + 8][jt * 32 + jj];
            float4 v0 = *(const float4*)&vt[d0][jj];
            float4 v1 = *(const float4*)&vt[d0 + 24][jj];
            acc[0][0] += p0.x*v0.x + p0.y*v0.y + p0.z*v0.z + p0.w*v0.w;
            acc[0][1] += p0.x*v1.x + p0.y*v1.y + p0.z*v1.z + p0.w*v1.w;
            acc[1][0] += p1.x*v0.x + p1.y*v0.y + p1.z*v0.z + p1.w*v0.w;
            acc[1][1] += p1.x*v1.x + p1.y*v1.y + p1.z*v1.z + p1.w*v1.w;
        }
        __syncthreads();
    }
    #pragma unroll
    for (int u = 0; u < 2; u++)
        #pragma unroll
        for (int w2 = 0; w2 < 2; w2++) {
            int i = ibase + ia + u * 8;
            int d = d0 + w2 * 24;
            size_t gi = (((size_t)b * II + i) * HH + h) * DD + d;
            float g = 1.f / (1.f + __expf(-gbuf[gi]));
            o[gi] = acc[u][w2] * g;
        }
}

// ---------------- host launch ----------------
static float* sym(const void* s) {
    void* p = nullptr;
    cudaGetSymbolAddress(&p, s);
    return (float*)p;
}

extern "C" void kernel_launch(void* const* d_in, const int* in_sizes, int n_in,
                              void* d_out, int out_size)
{
    const float* a_i      = (const float*)d_in[0];
    const float* s_i      = (const float*)d_in[1];
    const float* z_ij     = (const float*)d_in[2];
    const float* beta_ij  = (const float*)d_in[3];
    const float* lns_w    = (const float*)d_in[4];
    const float* lns_b    = (const float*)d_in[5];
    const float* Ws       = (const float*)d_in[6];
    const float* bs       = (const float*)d_in[7];
    const float* Wnb      = (const float*)d_in[8];
    const float* Wq       = (const float*)d_in[9];
    const float* bq       = (const float*)d_in[10];
    const float* Wk       = (const float*)d_in[11];
    const float* Wv       = (const float*)d_in[12];
    const float* lnb_w    = (const float*)d_in[13];
    const float* lnb_b    = (const float*)d_in[14];
    const float* Wb       = (const float*)d_in[15];
    const float* Wg       = (const float*)d_in[16];
    const float* Wo       = (const float*)d_in[17];
    const float* Ws_out   = (const float*)d_in[18];
    const float* bs_out   = (const float*)d_in[19];
    float* out = (float*)d_out;

    float* p_aln  = sym(g_aln);
    float* p_sln  = sym(g_sln);
    float* p_t1   = sym(g_t1);
    float* p_t2   = sym(g_t2);
    float* p_a2   = sym(g_a2);
    float* p_q    = sym(g_q);
    float* p_k    = sym(g_k);
    float* p_v    = sym(g_v);
    float* p_g    = sym(g_gbuf);
    float* p_gate = sym(g_gate);
    float* p_sc   = sym(g_scores);
    float* p_o    = sym(g_o);

    const int NEL = ROWS * CA;

    // pair bias first (independent of everything else)
    {
        dim3 g(II / 64, ROWS);
        pairbias_kernel<<<g, 256>>>(z_ij, beta_ij, lnb_w, lnb_b, Wb, p_sc);
    }

    // LayerNorms
    ln_kernel<<<ROWS, 256>>>(a_i, nullptr, nullptr, p_aln, CA);
    ln_kernel<<<ROWS, 256>>>(s_i, lns_w, lns_b, p_sln, CS);

    // AdaLN pair + output gate, all K=384, one batched launch
    {
        GemmBatch gb = {};
        gb.j[0] = { p_sln, Ws,     bs,      nullptr, p_t1,   0 };
        gb.j[1] = { p_sln, Wnb,    nullptr, nullptr, p_t2,   0 };
        gb.j[2] = { s_i,   Ws_out, bs_out,  nullptr, p_gate, 1 };
        dim3 g(CA / 64, ROWS / 128, 3);
        gemm_tc_kernel<<<g, 256>>>(gb, ROWS, CA, CS);
    }
    adaln_ew_kernel<<<(NEL + 255) / 256, 256>>>(p_t1, p_t2, p_aln, p_a2, NEL);

    // projections q,k,v,g (K=768)
    {
        GemmBatch gb = {};
        gb.j[0] = { p_a2, Wq, bq,      nullptr, p_q, 0 };
        gb.j[1] = { p_a2, Wk, nullptr, nullptr, p_k, 0 };
        gb.j[2] = { p_a2, Wv, nullptr, nullptr, p_v, 0 };
        gb.j[3] = { p_a2, Wg, nullptr, nullptr, p_g, 0 };
        dim3 g(HC / 64, ROWS / 128, 4);
        gemm_tc_kernel<<<g, 256>>>(gb, ROWS, HC, CA);
    }

    // scores += qk/sqrt(D)  (bf16x3, single-stage)
    {
        dim3 g(II / 64, II / 64, BB * HH);
        qk_tc_kernel<<<g, 128>>>(p_q, p_k, p_sc);
    }

    // softmax + AV + gate (scalar, proven)
    {
        dim3 g(II / 16, BB * HH);
        softmax_av_kernel<<<g, 192>>>(p_sc, p_v, p_g, p_o);
    }

    // out = gate * (o @ Wo)
    {
        GemmBatch gb = {};
        gb.j[0] = { p_o, Wo, nullptr, p_gate, out, 0 };
        dim3 g(CA / 64, ROWS / 128, 1);
        gemm_tc_kernel<<<g, 256>>>(gb, ROWS, CA, HC);
    }
}